// round 13
// baseline (speedup 1.0000x reference)
#include <cuda_runtime.h>
#include <cuda_bf16.h>
#include <math.h>
#include <stdint.h>

#define B_   2048
#define DIN  512
#define NS   256
#define NF   64
#define KTOT 768     // DIN + NS
#define NTOT 1088    // 256 + 64 + 256 + 256 + 256

// ---- scratch (device globals; no runtime allocation) ----
__device__ float g_fste [B_ * NS];
__device__ float g_ffreq[B_ * NF];
__device__ float g_id   [B_ * NS];
__device__ float g_cw   [B_ * NS];
__device__ float g_opre [B_ * NS];
__device__ float g_ct   [B_ * NS];
__device__ __nv_bfloat16 g_Ahi[(size_t)B_ * KTOT];
__device__ __nv_bfloat16 g_Alo[(size_t)B_ * KTOT];
__device__ __nv_bfloat16 g_Whi[(size_t)NTOT * KTOT];
__device__ __nv_bfloat16 g_Wlo[(size_t)NTOT * KTOT];

__device__ __forceinline__ float sigmoidf_(float z) { return 1.0f / (1.0f + __expf(-z)); }

__device__ __forceinline__ uint32_t smem_u32(const void* p) {
    uint32_t a;
    asm("{ .reg .u64 t; cvta.to.shared.u64 t, %1; cvt.u32.u64 %0, t; }" : "=r"(a) : "l"(p));
    return a;
}

// 64B-row swizzle: XOR 16B-chunk bits[5:4] with bits[8:7] (row>>1)
#define SW64(x) ((x) ^ (((x) >> 3) & 0x30))

#define CP16(dst, src) \
    asm volatile("cp.async.cg.shared.global [%0], [%1], 16;" :: "r"(dst), "l"(src))
#define CP_COMMIT() asm volatile("cp.async.commit_group;" ::: "memory")
#define CP_WAIT1()  asm volatile("cp.async.wait_group 1;" ::: "memory")

__device__ __forceinline__ void ldsm4(uint32_t r[4], uint32_t addr) {
    asm volatile("ldmatrix.sync.aligned.m8n8.x4.shared.b16 {%0,%1,%2,%3}, [%4];"
        : "=r"(r[0]), "=r"(r[1]), "=r"(r[2]), "=r"(r[3]) : "r"(addr));
}
__device__ __forceinline__ void mma_bf16(float c[4], const uint32_t a[4], const uint32_t b[2]) {
    asm volatile("mma.sync.aligned.m16n8k16.row.col.f32.bf16.bf16.f32 "
        "{%0,%1,%2,%3}, {%4,%5,%6,%7}, {%8,%9}, {%0,%1,%2,%3};"
        : "+f"(c[0]), "+f"(c[1]), "+f"(c[2]), "+f"(c[3])
        : "r"(a[0]), "r"(a[1]), "r"(a[2]), "r"(a[3]), "r"(b[0]), "r"(b[1]));
}

// ============================================================================
// Merged pack kernel: blocks [0, 1536) pack x_h, blocks [1536, 2352) pack W.
// ============================================================================
#define PACKX_BLOCKS ((B_ * KTOT) / (256 * 4))     // 1536
#define PACKW_BLOCKS ((KTOT / 32) * (NTOT / 32))   // 24 * 34 = 816

__global__ __launch_bounds__(256)
void pack_all_kernel(const float* __restrict__ x, const float* __restrict__ h,
                     const float* __restrict__ Wf, const float* __restrict__ Wff,
                     const float* __restrict__ Wi, const float* __restrict__ Wc,
                     const float* __restrict__ Wo)
{
    const int tid = threadIdx.x;
    if (blockIdx.x < PACKX_BLOCKS) {
        const int i = (blockIdx.x * 256 + tid) * 4;
        const int b = i / KTOT;
        const int k = i % KTOT;
        float4 v;
        if (k < DIN) v = *(const float4*)(x + (size_t)b * DIN + k);
        else         v = *(const float4*)(h + (size_t)b * NS + (k - DIN));
        float a[4] = {v.x, v.y, v.z, v.w};
#pragma unroll
        for (int j = 0; j < 4; j++) {
            __nv_bfloat16 hi = __float2bfloat16(a[j]);
            __nv_bfloat16 lo = __float2bfloat16(a[j] - __bfloat162float(hi));
            g_Ahi[(size_t)i + j] = hi;
            g_Alo[(size_t)i + j] = lo;
        }
    } else {
        __shared__ float tile[32][33];
        const int wb = blockIdx.x - PACKX_BLOCKS;
        const int k0 = (wb % (KTOT / 32)) * 32;
        const int n0 = (wb / (KTOT / 32)) * 32;
        const int tx = tid & 31;
        const int tyy = tid >> 5;      // 0..7
        for (int r = tyy; r < 32; r += 8) {
            const int k = k0 + r;
            const int n = n0 + tx;
            float v;
            if      (n < 256) v = Wf [(size_t)k * 256 + n];
            else if (n < 320) v = Wff[(size_t)k * 64  + (n - 256)];
            else if (n < 576) v = Wi [(size_t)k * 256 + (n - 320)];
            else if (n < 832) v = Wc [(size_t)k * 256 + (n - 576)];
            else              v = Wo [(size_t)k * 256 + (n - 832)];
            tile[r][tx] = v;
        }
        __syncthreads();
        for (int r = tyy; r < 32; r += 8) {
            const int n = n0 + r;
            const int k = k0 + tx;
            const float v = tile[tx][r];
            const __nv_bfloat16 hi = __float2bfloat16(v);
            g_Whi[(size_t)n * KTOT + k] = hi;
            g_Wlo[(size_t)n * KTOT + k] = __float2bfloat16(v - __bfloat162float(hi));
        }
    }
}

// ============================================================================
// Kernel 1: bf16x3 gate GEMM via mma.sync (HMMA). BM=128 BN=64 BK=32,
// 3-stage cp.async pipeline, ldmatrix + SW64 swizzle, fused segment epilogue.
// MMA issue order: 3 passes of 8 independent-acc MMAs (breaks acc RAW chains).
// ============================================================================
#define STAGE_BYTES 24576
#define NKSTEP (KTOT / 32)           // 24
#define MMA_SMEM_TOTAL (3 * STAGE_BYTES)

__global__ __launch_bounds__(256, 2)
void gemm1_mma_kernel(const float* __restrict__ b_fste, const float* __restrict__ b_ffreq,
                      const float* __restrict__ b_i, const float* __restrict__ b_c)
{
    extern __shared__ char smem[];
    const uint32_t sb = smem_u32(smem);
    const int tid = threadIdx.x;
    const int wid = tid >> 5;
    const int l   = tid & 31;
    const int wm  = wid >> 1;     // 0..3  (32-row slab)
    const int wn  = wid & 1;      // 0..1  (32-col slab)
    const int m0 = blockIdx.y * 128;
    const int n0 = blockIdx.x * 64;

    const int rA = (l & 7) + ((l >> 3) & 1) * 8;
    const int kA = ((l >> 4) & 1) * 16;
    const int rB = (l & 7) + ((l >> 4) & 1) * 8;
    const int kB = ((l >> 3) & 1) * 16;

    const int aRow0 = tid >> 2;
    const int aKc   = tid & 3;
    const int bRow  = tid >> 2;

    float acc[2][4][4];
#pragma unroll
    for (int i = 0; i < 2; i++)
#pragma unroll
        for (int j = 0; j < 4; j++)
#pragma unroll
            for (int q = 0; q < 4; q++) acc[i][j][q] = 0.0f;

#define LOAD_STAGE(ks_) do { \
    const int k0_ = (ks_) * 32; \
    const uint32_t st_ = sb + ((ks_) % 3) * STAGE_BYTES; \
    _Pragma("unroll") \
    for (int rep = 0; rep < 2; rep++) { \
        const int row = aRow0 + rep * 64; \
        const uint32_t d = st_ + SW64(row * 64 + aKc * 16); \
        CP16(d,        g_Ahi + (size_t)(m0 + row) * KTOT + k0_ + aKc * 8); \
        CP16(d + 8192, g_Alo + (size_t)(m0 + row) * KTOT + k0_ + aKc * 8); \
    } \
    { \
        const uint32_t d = st_ + 16384 + SW64(bRow * 64 + aKc * 16); \
        CP16(d,        g_Whi + (size_t)(n0 + bRow) * KTOT + k0_ + aKc * 8); \
        CP16(d + 4096, g_Wlo + (size_t)(n0 + bRow) * KTOT + k0_ + aKc * 8); \
    } \
} while (0)

    LOAD_STAGE(0); CP_COMMIT();
    LOAD_STAGE(1); CP_COMMIT();

    for (int ks = 0; ks < NKSTEP; ks++) {
        CP_WAIT1();
        __syncthreads();
        if (ks + 2 < NKSTEP) LOAD_STAGE(ks + 2);
        CP_COMMIT();

        const uint32_t st = sb + (ks % 3) * STAGE_BYTES;
#pragma unroll
        for (int k16 = 0; k16 < 2; k16++) {
            uint32_t ah[2][4], al[2][4], bh[4][2], bl[4][2];
#pragma unroll
            for (int ma = 0; ma < 2; ma++) {
                const uint32_t off = SW64((wm * 32 + ma * 16 + rA) * 64 + kA + k16 * 32);
                ldsm4(ah[ma], st + off);
                ldsm4(al[ma], st + 8192 + off);
            }
#pragma unroll
            for (int p = 0; p < 2; p++) {
                const uint32_t off = 16384 + SW64((wn * 32 + p * 16 + rB) * 64 + kB + k16 * 32);
                uint32_t q[4];
                ldsm4(q, st + off);
                bh[2 * p][0] = q[0]; bh[2 * p][1] = q[1];
                bh[2 * p + 1][0] = q[2]; bh[2 * p + 1][1] = q[3];
                ldsm4(q, st + 4096 + off);
                bl[2 * p][0] = q[0]; bl[2 * p][1] = q[1];
                bl[2 * p + 1][0] = q[2]; bl[2 * p + 1][1] = q[3];
            }
            // pass 1: hi*hi — 8 independent accumulators
#pragma unroll
            for (int ma = 0; ma < 2; ma++)
#pragma unroll
                for (int na = 0; na < 4; na++)
                    mma_bf16(acc[ma][na], ah[ma], bh[na]);
            // pass 2: hi*lo
#pragma unroll
            for (int ma = 0; ma < 2; ma++)
#pragma unroll
                for (int na = 0; na < 4; na++)
                    mma_bf16(acc[ma][na], ah[ma], bl[na]);
            // pass 3: lo*hi
#pragma unroll
            for (int ma = 0; ma < 2; ma++)
#pragma unroll
                for (int na = 0; na < 4; na++)
                    mma_bf16(acc[ma][na], al[ma], bh[na]);
        }
    }

    // --- fused segment epilogue ---
    float* dst; const float* bias; int colw, coloff, act;
    if      (n0 < 256) { dst = g_fste;  bias = b_fste;  colw = NS; coloff = n0;       act = 0; }
    else if (n0 < 320) { dst = g_ffreq; bias = b_ffreq; colw = NF; coloff = n0 - 256; act = 0; }
    else if (n0 < 576) { dst = g_id;    bias = b_i;     colw = NS; coloff = n0 - 320; act = 0; }
    else if (n0 < 832) { dst = g_cw;    bias = b_c;     colw = NS; coloff = n0 - 576; act = 1; }
    else               { dst = g_opre;  bias = b_fste;  colw = NS; coloff = n0 - 832; act = 2; }

#pragma unroll
    for (int ma = 0; ma < 2; ma++) {
#pragma unroll
        for (int half = 0; half < 2; half++) {
            const int gm = m0 + wm * 32 + ma * 16 + (l >> 2) + half * 8;
#pragma unroll
            for (int na = 0; na < 4; na++) {
                const int col = wn * 32 + na * 8 + (l & 3) * 2;
                float v0 = acc[ma][na][half * 2 + 0];
                float v1 = acc[ma][na][half * 2 + 1];
                if (act == 0) {
                    v0 = sigmoidf_(v0 + bias[coloff + col]);
                    v1 = sigmoidf_(v1 + bias[coloff + col + 1]);
                } else if (act == 1) {
                    v0 = tanhf(v0 + bias[coloff + col]);
                    v1 = tanhf(v1 + bias[coloff + col + 1]);
                }
                *(float2*)(dst + (size_t)gm * colw + coloff + col) = make_float2(v0, v1);
            }
        }
    }
#undef LOAD_STAGE
}

// ============================================================================
// Kernel 2: fused S update + amplitude reduction + c_t.
// 4 rows/warp, MLP=8 loads; stores use __stcs (S_out written once, never read).
// ============================================================================
__global__ __launch_bounds__(256)
void s_update_kernel(const float* __restrict__ S_in, float* __restrict__ S_out,
                     const float* __restrict__ u_a, const float* __restrict__ b_a,
                     const int* __restrict__ t_ptr)
{
    const uint32_t warp = (blockIdx.x * 256u + threadIdx.x) >> 5;   // [0, B_*NS/4)
    const uint32_t lane = threadIdx.x & 31u;
    const uint32_t r0 = warp << 2;
    const uint32_t b  = r0 >> 8;
    const uint32_t i0 = r0 & 255u;
    const uint32_t j0 = lane << 1;

    const uint32_t base00 = (b << 15) + (i0 << 6) + j0;
    float2 sv[4][2];
#pragma unroll
    for (int q = 0; q < 4; q++) {
        sv[q][0] = *(const float2*)(S_in + base00 + (uint32_t)(q << 6));
        sv[q][1] = *(const float2*)(S_in + base00 + (uint32_t)(q << 6) + (1u << 14));
    }

    float fs[4], ic[4];
#pragma unroll
    for (int q = 0; q < 4; q++) {
        fs[q] = g_fste[r0 + q];
        ic[q] = g_id[r0 + q] * g_cw[r0 + q];
    }
    const float2 ff = *(const float2*)(g_ffreq + (b << 6) + j0);

    const int t = *t_ptr;
    const int m0 = ((int)j0 * t) & 63;
    const int m1 = ((int)(j0 + 1) * t) & 63;
    const float C = 0.098174770424681038798f;  // 2*pi/64
    float s0a, c0a, s1a, c1a;
    __sincosf((float)m0 * C, &s0a, &c0a);
    __sincosf((float)m1 * C, &s1a, &c1a);

    const float2 ua = *(const float2*)(u_a + j0);

    float accv[4];
#pragma unroll
    for (int q = 0; q < 4; q++) {
        const float f0 = fs[q] * ff.x;
        const float f1 = fs[q] * ff.y;
        float2 sn0, sn1;
        sn0.x = sv[q][0].x * f0 + ic[q] * s0a;
        sn0.y = sv[q][0].y * f1 + ic[q] * s1a;
        sn1.x = sv[q][1].x * f0 + ic[q] * c0a;
        sn1.y = sv[q][1].y * f1 + ic[q] * c1a;
        __stcs((float2*)(S_out + base00 + (uint32_t)(q << 6)), sn0);
        __stcs((float2*)(S_out + base00 + (uint32_t)(q << 6) + (1u << 14)), sn1);
        accv[q] = sqrtf(sn0.x * sn0.x + sn1.x * sn1.x) * ua.x
                + sqrtf(sn0.y * sn0.y + sn1.y * sn1.y) * ua.y;
    }

#pragma unroll
    for (int off = 16; off; off >>= 1) {
#pragma unroll
        for (int q = 0; q < 4; q++)
            accv[q] += __shfl_xor_sync(0xffffffff, accv[q], off);
    }

    if (lane == 0) {
#pragma unroll
        for (int q = 0; q < 4; q++)
            g_ct[r0 + q] = sigmoidf_(accv[q] + b_a[i0 + q]);
    }
}

// ============================================================================
// Kernel 3: output GEMM, register-double-buffered smem pipeline. (R11 exact)
// BM=32 BN=64 BK=32 TM=2 TN=4, 256 thr, grid (4,64)=256 CTAs, 8 K-iters.
// ============================================================================
__global__ __launch_bounds__(256)
void gemm3_kernel(const float* __restrict__ W_o, const float* __restrict__ b_o,
                  float* __restrict__ h_out)
{
    constexpr int BM = 32, BN = 64, BK = 32, TM = 2, TN = 4;
    constexpr int NIT = NS / BK;   // 8
    __shared__ float As[2][BK][BM + 1];
    __shared__ float Bs[2][BK][BN + 4];

    const int tid = threadIdx.x;
    const int m0 = blockIdx.y * BM;
    const int n0 = blockIdx.x * BN;
    const int tx = tid & 15;     // 16 cols * TN=4 -> 64
    const int ty = tid >> 4;     // 16 rows * TM=2 -> 32

    const float* Wc = W_o + (size_t)KTOT * 256;

    const int ar = tid >> 3;          // 0..31 (A row)
    const int ac = (tid & 7) * 4;     // 0..28 (A k-col, float4)
    const int br = tid >> 4;          // 0..15 (B k-row; +16 for rep)
    const int bc = (tid & 15) * 4;    // 0..60 (B n-col, float4)

    float acc[TM][TN];
#pragma unroll
    for (int i = 0; i < TM; i++)
#pragma unroll
        for (int j = 0; j < TN; j++) acc[i][j] = 0.0f;

    float4 pa, pb0, pb1;

    pa  = *(const float4*)(g_ct + (size_t)(m0 + ar) * NS + ac);
    pb0 = *(const float4*)(Wc + (size_t)br * 256 + n0 + bc);
    pb1 = *(const float4*)(Wc + (size_t)(br + 16) * 256 + n0 + bc);
    As[0][ac + 0][ar] = pa.x; As[0][ac + 1][ar] = pa.y;
    As[0][ac + 2][ar] = pa.z; As[0][ac + 3][ar] = pa.w;
    Bs[0][br][bc + 0] = pb0.x; Bs[0][br][bc + 1] = pb0.y;
    Bs[0][br][bc + 2] = pb0.z; Bs[0][br][bc + 3] = pb0.w;
    Bs[0][br + 16][bc + 0] = pb1.x; Bs[0][br + 16][bc + 1] = pb1.y;
    Bs[0][br + 16][bc + 2] = pb1.z; Bs[0][br + 16][bc + 3] = pb1.w;
    __syncthreads();

    for (int it = 0; it < NIT; it++) {
        const int s = it & 1;
        if (it + 1 < NIT) {
            const int k0 = (it + 1) * BK;
            pa  = *(const float4*)(g_ct + (size_t)(m0 + ar) * NS + k0 + ac);
            pb0 = *(const float4*)(Wc + (size_t)(k0 + br) * 256 + n0 + bc);
            pb1 = *(const float4*)(Wc + (size_t)(k0 + br + 16) * 256 + n0 + bc);
        }

#pragma unroll
        for (int kk = 0; kk < BK; kk++) {
            float ra[TM], rb[TN];
#pragma unroll
            for (int i = 0; i < TM; i++) ra[i] = As[s][kk][ty * TM + i];
#pragma unroll
            for (int j = 0; j < TN; j++) rb[j] = Bs[s][kk][tx * TN + j];
#pragma unroll
            for (int i = 0; i < TM; i++)
#pragma unroll
                for (int j = 0; j < TN; j++) acc[i][j] = fmaf(ra[i], rb[j], acc[i][j]);
        }

        if (it + 1 < NIT) {
            const int d = s ^ 1;
            As[d][ac + 0][ar] = pa.x; As[d][ac + 1][ar] = pa.y;
            As[d][ac + 2][ar] = pa.z; As[d][ac + 3][ar] = pa.w;
            Bs[d][br][bc + 0] = pb0.x; Bs[d][br][bc + 1] = pb0.y;
            Bs[d][br][bc + 2] = pb0.z; Bs[d][br][bc + 3] = pb0.w;
            Bs[d][br + 16][bc + 0] = pb1.x; Bs[d][br + 16][bc + 1] = pb1.y;
            Bs[d][br + 16][bc + 2] = pb1.z; Bs[d][br + 16][bc + 3] = pb1.w;
            __syncthreads();
        }
    }

#pragma unroll
    for (int i = 0; i < TM; i++) {
        const int gm = m0 + ty * TM + i;
#pragma unroll
        for (int j = 0; j < TN; j++) {
            const int gn = n0 + tx * TN + j;
            const float z = acc[i][j] + g_opre[(size_t)gm * NS + gn] + b_o[gn];
            const float ct = g_ct[(size_t)gm * NS + gn];
            h_out[(size_t)gm * NS + gn] = sigmoidf_(z) * ct;
        }
    }
}

// ============================================================================
extern "C" void kernel_launch(void* const* d_in, const int* in_sizes, int n_in,
                              void* d_out, int out_size)
{
    const float* x_i     = (const float*)d_in[0];
    const float* h_i     = (const float*)d_in[1];
    const float* S_i     = (const float*)d_in[2];
    const float* W_fste  = (const float*)d_in[3];
    const float* b_fste  = (const float*)d_in[4];
    const float* W_ffreq = (const float*)d_in[5];
    const float* b_ffreq = (const float*)d_in[6];
    const float* W_i     = (const float*)d_in[7];
    const float* b_i     = (const float*)d_in[8];
    const float* W_c     = (const float*)d_in[9];
    const float* b_c     = (const float*)d_in[10];
    const float* u_a     = (const float*)d_in[11];
    const float* b_a     = (const float*)d_in[12];
    const float* W_o     = (const float*)d_in[13];
    const float* b_o     = (const float*)d_in[14];
    const int*   t_ptr   = (const int*)d_in[15];

    float* out = (float*)d_out;
    float* h_out = out;                        // [B, NS]
    float* S_out = out + (size_t)B_ * NS;      // [B, 2, NS, NF]

    cudaFuncSetAttribute(gemm1_mma_kernel, cudaFuncAttributeMaxDynamicSharedMemorySize,
                         MMA_SMEM_TOTAL);

    // 0) pack operands to bf16 hi/lo (single launch)
    pack_all_kernel<<<PACKX_BLOCKS + PACKW_BLOCKS, 256>>>(x_i, h_i, W_fste, W_ffreq,
                                                          W_i, W_c, W_o);
    // 1) gate GEMM on HMMA tensor cores (bf16x3, 3-pass MMA order)
    {
        dim3 grid(NTOT / 64, B_ / 128);        // (17, 16)
        gemm1_mma_kernel<<<grid, 256, MMA_SMEM_TOTAL>>>(b_fste, b_ffreq, b_i, b_c);
    }
    // 2) fused S update + amplitude reduction + c_t (4 rows/warp, stcs stores)
    {
        const int warps = B_ * NS / 4;
        dim3 grid(warps / 8);
        s_update_kernel<<<grid, 256>>>(S_i, S_out, u_a, b_a, t_ptr);
    }
    // 3) output GEMM + final elementwise (R11-exact BM=32 shape)
    {
        dim3 grid(NS / 64, B_ / 32);           // (4, 64) = 256 CTAs
        gemm3_kernel<<<grid, 256>>>(W_o, b_o, h_out);
    }
}

// round 14
// speedup vs baseline: 1.2763x; 1.2763x over previous
#include <cuda_runtime.h>
#include <cuda_bf16.h>
#include <math.h>
#include <stdint.h>

#define B_   2048
#define DIN  512
#define NS   256
#define NF   64
#define KTOT 768     // DIN + NS
#define NTOT 1088    // 256 + 64 + 256 + 256 + 256

// ---- scratch (device globals; no runtime allocation) ----
__device__ float g_fste [B_ * NS];
__device__ float g_ffreq[B_ * NF];
__device__ float g_id   [B_ * NS];
__device__ float g_cw   [B_ * NS];
__device__ float g_opre [B_ * NS];
__device__ float g_ct   [B_ * NS];
__device__ __nv_bfloat16 g_Ahi[(size_t)B_ * KTOT];
__device__ __nv_bfloat16 g_Alo[(size_t)B_ * KTOT];
__device__ __nv_bfloat16 g_Whi[(size_t)NTOT * KTOT];
__device__ __nv_bfloat16 g_Wlo[(size_t)NTOT * KTOT];

__device__ __forceinline__ float sigmoidf_(float z) { return 1.0f / (1.0f + __expf(-z)); }

__device__ __forceinline__ uint32_t smem_u32(const void* p) {
    uint32_t a;
    asm("{ .reg .u64 t; cvta.to.shared.u64 t, %1; cvt.u32.u64 %0, t; }" : "=r"(a) : "l"(p));
    return a;
}

// 64B-row swizzle: XOR 16B-chunk bits[5:4] with bits[8:7] (row>>1)
#define SW64(x) ((x) ^ (((x) >> 3) & 0x30))

#define CP16(dst, src) \
    asm volatile("cp.async.cg.shared.global [%0], [%1], 16;" :: "r"(dst), "l"(src))
#define CP_COMMIT() asm volatile("cp.async.commit_group;" ::: "memory")
#define CP_WAIT1()  asm volatile("cp.async.wait_group 1;" ::: "memory")

__device__ __forceinline__ void ldsm4(uint32_t r[4], uint32_t addr) {
    asm volatile("ldmatrix.sync.aligned.m8n8.x4.shared.b16 {%0,%1,%2,%3}, [%4];"
        : "=r"(r[0]), "=r"(r[1]), "=r"(r[2]), "=r"(r[3]) : "r"(addr));
}
__device__ __forceinline__ void mma_bf16(float c[4], const uint32_t a[4], const uint32_t b[2]) {
    asm volatile("mma.sync.aligned.m16n8k16.row.col.f32.bf16.bf16.f32 "
        "{%0,%1,%2,%3}, {%4,%5,%6,%7}, {%8,%9}, {%0,%1,%2,%3};"
        : "+f"(c[0]), "+f"(c[1]), "+f"(c[2]), "+f"(c[3])
        : "r"(a[0]), "r"(a[1]), "r"(a[2]), "r"(a[3]), "r"(b[0]), "r"(b[1]));
}

// ============================================================================
// Merged pack kernel: blocks [0, 1536) pack x_h, blocks [1536, 2352) pack W.
// ============================================================================
#define PACKX_BLOCKS ((B_ * KTOT) / (256 * 4))     // 1536
#define PACKW_BLOCKS ((KTOT / 32) * (NTOT / 32))   // 24 * 34 = 816

__global__ __launch_bounds__(256)
void pack_all_kernel(const float* __restrict__ x, const float* __restrict__ h,
                     const float* __restrict__ Wf, const float* __restrict__ Wff,
                     const float* __restrict__ Wi, const float* __restrict__ Wc,
                     const float* __restrict__ Wo)
{
    const int tid = threadIdx.x;
    if (blockIdx.x < PACKX_BLOCKS) {
        const int i = (blockIdx.x * 256 + tid) * 4;
        const int b = i / KTOT;
        const int k = i % KTOT;
        float4 v;
        if (k < DIN) v = *(const float4*)(x + (size_t)b * DIN + k);
        else         v = *(const float4*)(h + (size_t)b * NS + (k - DIN));
        float a[4] = {v.x, v.y, v.z, v.w};
#pragma unroll
        for (int j = 0; j < 4; j++) {
            __nv_bfloat16 hi = __float2bfloat16(a[j]);
            __nv_bfloat16 lo = __float2bfloat16(a[j] - __bfloat162float(hi));
            g_Ahi[(size_t)i + j] = hi;
            g_Alo[(size_t)i + j] = lo;
        }
    } else {
        __shared__ float tile[32][33];
        const int wb = blockIdx.x - PACKX_BLOCKS;
        const int k0 = (wb % (KTOT / 32)) * 32;
        const int n0 = (wb / (KTOT / 32)) * 32;
        const int tx = tid & 31;
        const int tyy = tid >> 5;      // 0..7
        for (int r = tyy; r < 32; r += 8) {
            const int k = k0 + r;
            const int n = n0 + tx;
            float v;
            if      (n < 256) v = Wf [(size_t)k * 256 + n];
            else if (n < 320) v = Wff[(size_t)k * 64  + (n - 256)];
            else if (n < 576) v = Wi [(size_t)k * 256 + (n - 320)];
            else if (n < 832) v = Wc [(size_t)k * 256 + (n - 576)];
            else              v = Wo [(size_t)k * 256 + (n - 832)];
            tile[r][tx] = v;
        }
        __syncthreads();
        for (int r = tyy; r < 32; r += 8) {
            const int n = n0 + r;
            const int k = k0 + tx;
            const float v = tile[tx][r];
            const __nv_bfloat16 hi = __float2bfloat16(v);
            g_Whi[(size_t)n * KTOT + k] = hi;
            g_Wlo[(size_t)n * KTOT + k] = __float2bfloat16(v - __bfloat162float(hi));
        }
    }
}

// ============================================================================
// Kernel 1: bf16x3 gate GEMM via mma.sync (HMMA). BM=128 BN=64 BK=32,
// 3-stage cp.async pipeline, ldmatrix + SW64 swizzle, fused segment epilogue.
// Interleaved MMA order (R11-exact; 3-pass reorder was a regression).
// ============================================================================
#define STAGE_BYTES 24576
#define NKSTEP (KTOT / 32)           // 24
#define MMA_SMEM_TOTAL (3 * STAGE_BYTES)

__global__ __launch_bounds__(256, 2)
void gemm1_mma_kernel(const float* __restrict__ b_fste, const float* __restrict__ b_ffreq,
                      const float* __restrict__ b_i, const float* __restrict__ b_c)
{
    extern __shared__ char smem[];
    const uint32_t sb = smem_u32(smem);
    const int tid = threadIdx.x;
    const int wid = tid >> 5;
    const int l   = tid & 31;
    const int wm  = wid >> 1;     // 0..3  (32-row slab)
    const int wn  = wid & 1;      // 0..1  (32-col slab)
    const int m0 = blockIdx.y * 128;
    const int n0 = blockIdx.x * 64;

    const int rA = (l & 7) + ((l >> 3) & 1) * 8;
    const int kA = ((l >> 4) & 1) * 16;
    const int rB = (l & 7) + ((l >> 4) & 1) * 8;
    const int kB = ((l >> 3) & 1) * 16;

    const int aRow0 = tid >> 2;
    const int aKc   = tid & 3;
    const int bRow  = tid >> 2;

    float acc[2][4][4];
#pragma unroll
    for (int i = 0; i < 2; i++)
#pragma unroll
        for (int j = 0; j < 4; j++)
#pragma unroll
            for (int q = 0; q < 4; q++) acc[i][j][q] = 0.0f;

#define LOAD_STAGE(ks_) do { \
    const int k0_ = (ks_) * 32; \
    const uint32_t st_ = sb + ((ks_) % 3) * STAGE_BYTES; \
    _Pragma("unroll") \
    for (int rep = 0; rep < 2; rep++) { \
        const int row = aRow0 + rep * 64; \
        const uint32_t d = st_ + SW64(row * 64 + aKc * 16); \
        CP16(d,        g_Ahi + (size_t)(m0 + row) * KTOT + k0_ + aKc * 8); \
        CP16(d + 8192, g_Alo + (size_t)(m0 + row) * KTOT + k0_ + aKc * 8); \
    } \
    { \
        const uint32_t d = st_ + 16384 + SW64(bRow * 64 + aKc * 16); \
        CP16(d,        g_Whi + (size_t)(n0 + bRow) * KTOT + k0_ + aKc * 8); \
        CP16(d + 4096, g_Wlo + (size_t)(n0 + bRow) * KTOT + k0_ + aKc * 8); \
    } \
} while (0)

    LOAD_STAGE(0); CP_COMMIT();
    LOAD_STAGE(1); CP_COMMIT();

    for (int ks = 0; ks < NKSTEP; ks++) {
        CP_WAIT1();
        __syncthreads();
        if (ks + 2 < NKSTEP) LOAD_STAGE(ks + 2);
        CP_COMMIT();

        const uint32_t st = sb + (ks % 3) * STAGE_BYTES;
#pragma unroll
        for (int k16 = 0; k16 < 2; k16++) {
            uint32_t ah[2][4], al[2][4], bh[4][2], bl[4][2];
#pragma unroll
            for (int ma = 0; ma < 2; ma++) {
                const uint32_t off = SW64((wm * 32 + ma * 16 + rA) * 64 + kA + k16 * 32);
                ldsm4(ah[ma], st + off);
                ldsm4(al[ma], st + 8192 + off);
            }
#pragma unroll
            for (int p = 0; p < 2; p++) {
                const uint32_t off = 16384 + SW64((wn * 32 + p * 16 + rB) * 64 + kB + k16 * 32);
                uint32_t q[4];
                ldsm4(q, st + off);
                bh[2 * p][0] = q[0]; bh[2 * p][1] = q[1];
                bh[2 * p + 1][0] = q[2]; bh[2 * p + 1][1] = q[3];
                ldsm4(q, st + 4096 + off);
                bl[2 * p][0] = q[0]; bl[2 * p][1] = q[1];
                bl[2 * p + 1][0] = q[2]; bl[2 * p + 1][1] = q[3];
            }
#pragma unroll
            for (int ma = 0; ma < 2; ma++)
#pragma unroll
                for (int na = 0; na < 4; na++) {
                    mma_bf16(acc[ma][na], ah[ma], bh[na]);
                    mma_bf16(acc[ma][na], ah[ma], bl[na]);
                    mma_bf16(acc[ma][na], al[ma], bh[na]);
                }
        }
    }

    // --- fused segment epilogue ---
    float* dst; const float* bias; int colw, coloff, act;
    if      (n0 < 256) { dst = g_fste;  bias = b_fste;  colw = NS; coloff = n0;       act = 0; }
    else if (n0 < 320) { dst = g_ffreq; bias = b_ffreq; colw = NF; coloff = n0 - 256; act = 0; }
    else if (n0 < 576) { dst = g_id;    bias = b_i;     colw = NS; coloff = n0 - 320; act = 0; }
    else if (n0 < 832) { dst = g_cw;    bias = b_c;     colw = NS; coloff = n0 - 576; act = 1; }
    else               { dst = g_opre;  bias = b_fste;  colw = NS; coloff = n0 - 832; act = 2; }

#pragma unroll
    for (int ma = 0; ma < 2; ma++) {
#pragma unroll
        for (int half = 0; half < 2; half++) {
            const int gm = m0 + wm * 32 + ma * 16 + (l >> 2) + half * 8;
#pragma unroll
            for (int na = 0; na < 4; na++) {
                const int col = wn * 32 + na * 8 + (l & 3) * 2;
                float v0 = acc[ma][na][half * 2 + 0];
                float v1 = acc[ma][na][half * 2 + 1];
                if (act == 0) {
                    v0 = sigmoidf_(v0 + bias[coloff + col]);
                    v1 = sigmoidf_(v1 + bias[coloff + col + 1]);
                } else if (act == 1) {
                    v0 = tanhf(v0 + bias[coloff + col]);
                    v1 = tanhf(v1 + bias[coloff + col + 1]);
                }
                *(float2*)(dst + (size_t)gm * colw + coloff + col) = make_float2(v0, v1);
            }
        }
    }
#undef LOAD_STAGE
}

// ============================================================================
// Kernel 2: fused S update + amplitude reduction + c_t.
// 4 rows/warp, MLP=8 loads; __stcs stores (S_out written once, never read).
// ============================================================================
__global__ __launch_bounds__(256)
void s_update_kernel(const float* __restrict__ S_in, float* __restrict__ S_out,
                     const float* __restrict__ u_a, const float* __restrict__ b_a,
                     const int* __restrict__ t_ptr)
{
    const uint32_t warp = (blockIdx.x * 256u + threadIdx.x) >> 5;   // [0, B_*NS/4)
    const uint32_t lane = threadIdx.x & 31u;
    const uint32_t r0 = warp << 2;
    const uint32_t b  = r0 >> 8;
    const uint32_t i0 = r0 & 255u;
    const uint32_t j0 = lane << 1;

    const uint32_t base00 = (b << 15) + (i0 << 6) + j0;
    float2 sv[4][2];
#pragma unroll
    for (int q = 0; q < 4; q++) {
        sv[q][0] = *(const float2*)(S_in + base00 + (uint32_t)(q << 6));
        sv[q][1] = *(const float2*)(S_in + base00 + (uint32_t)(q << 6) + (1u << 14));
    }

    float fs[4], ic[4];
#pragma unroll
    for (int q = 0; q < 4; q++) {
        fs[q] = g_fste[r0 + q];
        ic[q] = g_id[r0 + q] * g_cw[r0 + q];
    }
    const float2 ff = *(const float2*)(g_ffreq + (b << 6) + j0);

    const int t = *t_ptr;
    const int m0 = ((int)j0 * t) & 63;
    const int m1 = ((int)(j0 + 1) * t) & 63;
    const float C = 0.098174770424681038798f;  // 2*pi/64
    float s0a, c0a, s1a, c1a;
    __sincosf((float)m0 * C, &s0a, &c0a);
    __sincosf((float)m1 * C, &s1a, &c1a);

    const float2 ua = *(const float2*)(u_a + j0);

    float accv[4];
#pragma unroll
    for (int q = 0; q < 4; q++) {
        const float f0 = fs[q] * ff.x;
        const float f1 = fs[q] * ff.y;
        float2 sn0, sn1;
        sn0.x = sv[q][0].x * f0 + ic[q] * s0a;
        sn0.y = sv[q][0].y * f1 + ic[q] * s1a;
        sn1.x = sv[q][1].x * f0 + ic[q] * c0a;
        sn1.y = sv[q][1].y * f1 + ic[q] * c1a;
        __stcs((float2*)(S_out + base00 + (uint32_t)(q << 6)), sn0);
        __stcs((float2*)(S_out + base00 + (uint32_t)(q << 6) + (1u << 14)), sn1);
        accv[q] = sqrtf(sn0.x * sn0.x + sn1.x * sn1.x) * ua.x
                + sqrtf(sn0.y * sn0.y + sn1.y * sn1.y) * ua.y;
    }

#pragma unroll
    for (int off = 16; off; off >>= 1) {
#pragma unroll
        for (int q = 0; q < 4; q++)
            accv[q] += __shfl_xor_sync(0xffffffff, accv[q], off);
    }

    if (lane == 0) {
#pragma unroll
        for (int q = 0; q < 4; q++)
            g_ct[r0 + q] = sigmoidf_(accv[q] + b_a[i0 + q]);
    }
}

// ============================================================================
// Kernel 3: output GEMM, register-double-buffered smem pipeline. (R11 exact)
// BM=32 BN=64 BK=32 TM=2 TN=4, 256 thr, grid (4,64)=256 CTAs, 8 K-iters.
// ============================================================================
__global__ __launch_bounds__(256)
void gemm3_kernel(const float* __restrict__ W_o, const float* __restrict__ b_o,
                  float* __restrict__ h_out)
{
    constexpr int BM = 32, BN = 64, BK = 32, TM = 2, TN = 4;
    constexpr int NIT = NS / BK;   // 8
    __shared__ float As[2][BK][BM + 1];
    __shared__ float Bs[2][BK][BN + 4];

    const int tid = threadIdx.x;
    const int m0 = blockIdx.y * BM;
    const int n0 = blockIdx.x * BN;
    const int tx = tid & 15;     // 16 cols * TN=4 -> 64
    const int ty = tid >> 4;     // 16 rows * TM=2 -> 32

    const float* Wc = W_o + (size_t)KTOT * 256;

    const int ar = tid >> 3;          // 0..31 (A row)
    const int ac = (tid & 7) * 4;     // 0..28 (A k-col, float4)
    const int br = tid >> 4;          // 0..15 (B k-row; +16 for rep)
    const int bc = (tid & 15) * 4;    // 0..60 (B n-col, float4)

    float acc[TM][TN];
#pragma unroll
    for (int i = 0; i < TM; i++)
#pragma unroll
        for (int j = 0; j < TN; j++) acc[i][j] = 0.0f;

    float4 pa, pb0, pb1;

    pa  = *(const float4*)(g_ct + (size_t)(m0 + ar) * NS + ac);
    pb0 = *(const float4*)(Wc + (size_t)br * 256 + n0 + bc);
    pb1 = *(const float4*)(Wc + (size_t)(br + 16) * 256 + n0 + bc);
    As[0][ac + 0][ar] = pa.x; As[0][ac + 1][ar] = pa.y;
    As[0][ac + 2][ar] = pa.z; As[0][ac + 3][ar] = pa.w;
    Bs[0][br][bc + 0] = pb0.x; Bs[0][br][bc + 1] = pb0.y;
    Bs[0][br][bc + 2] = pb0.z; Bs[0][br][bc + 3] = pb0.w;
    Bs[0][br + 16][bc + 0] = pb1.x; Bs[0][br + 16][bc + 1] = pb1.y;
    Bs[0][br + 16][bc + 2] = pb1.z; Bs[0][br + 16][bc + 3] = pb1.w;
    __syncthreads();

    for (int it = 0; it < NIT; it++) {
        const int s = it & 1;
        if (it + 1 < NIT) {
            const int k0 = (it + 1) * BK;
            pa  = *(const float4*)(g_ct + (size_t)(m0 + ar) * NS + k0 + ac);
            pb0 = *(const float4*)(Wc + (size_t)(k0 + br) * 256 + n0 + bc);
            pb1 = *(const float4*)(Wc + (size_t)(k0 + br + 16) * 256 + n0 + bc);
        }

#pragma unroll
        for (int kk = 0; kk < BK; kk++) {
            float ra[TM], rb[TN];
#pragma unroll
            for (int i = 0; i < TM; i++) ra[i] = As[s][kk][ty * TM + i];
#pragma unroll
            for (int j = 0; j < TN; j++) rb[j] = Bs[s][kk][tx * TN + j];
#pragma unroll
            for (int i = 0; i < TM; i++)
#pragma unroll
                for (int j = 0; j < TN; j++) acc[i][j] = fmaf(ra[i], rb[j], acc[i][j]);
        }

        if (it + 1 < NIT) {
            const int d = s ^ 1;
            As[d][ac + 0][ar] = pa.x; As[d][ac + 1][ar] = pa.y;
            As[d][ac + 2][ar] = pa.z; As[d][ac + 3][ar] = pa.w;
            Bs[d][br][bc + 0] = pb0.x; Bs[d][br][bc + 1] = pb0.y;
            Bs[d][br][bc + 2] = pb0.z; Bs[d][br][bc + 3] = pb0.w;
            Bs[d][br + 16][bc + 0] = pb1.x; Bs[d][br + 16][bc + 1] = pb1.y;
            Bs[d][br + 16][bc + 2] = pb1.z; Bs[d][br + 16][bc + 3] = pb1.w;
            __syncthreads();
        }
    }

#pragma unroll
    for (int i = 0; i < TM; i++) {
        const int gm = m0 + ty * TM + i;
#pragma unroll
        for (int j = 0; j < TN; j++) {
            const int gn = n0 + tx * TN + j;
            const float z = acc[i][j] + g_opre[(size_t)gm * NS + gn] + b_o[gn];
            const float ct = g_ct[(size_t)gm * NS + gn];
            h_out[(size_t)gm * NS + gn] = sigmoidf_(z) * ct;
        }
    }
}

// ============================================================================
extern "C" void kernel_launch(void* const* d_in, const int* in_sizes, int n_in,
                              void* d_out, int out_size)
{
    const float* x_i     = (const float*)d_in[0];
    const float* h_i     = (const float*)d_in[1];
    const float* S_i     = (const float*)d_in[2];
    const float* W_fste  = (const float*)d_in[3];
    const float* b_fste  = (const float*)d_in[4];
    const float* W_ffreq = (const float*)d_in[5];
    const float* b_ffreq = (const float*)d_in[6];
    const float* W_i     = (const float*)d_in[7];
    const float* b_i     = (const float*)d_in[8];
    const float* W_c     = (const float*)d_in[9];
    const float* b_c     = (const float*)d_in[10];
    const float* u_a     = (const float*)d_in[11];
    const float* b_a     = (const float*)d_in[12];
    const float* W_o     = (const float*)d_in[13];
    const float* b_o     = (const float*)d_in[14];
    const int*   t_ptr   = (const int*)d_in[15];

    float* out = (float*)d_out;
    float* h_out = out;                        // [B, NS]
    float* S_out = out + (size_t)B_ * NS;      // [B, 2, NS, NF]

    cudaFuncSetAttribute(gemm1_mma_kernel, cudaFuncAttributeMaxDynamicSharedMemorySize,
                         MMA_SMEM_TOTAL);

    // 0) pack operands to bf16 hi/lo (single launch)
    pack_all_kernel<<<PACKX_BLOCKS + PACKW_BLOCKS, 256>>>(x_i, h_i, W_fste, W_ffreq,
                                                          W_i, W_c, W_o);
    // 1) gate GEMM on HMMA tensor cores (bf16x3, interleaved MMA order)
    {
        dim3 grid(NTOT / 64, B_ / 128);        // (17, 16)
        gemm1_mma_kernel<<<grid, 256, MMA_SMEM_TOTAL>>>(b_fste, b_ffreq, b_i, b_c);
    }
    // 2) fused S update + amplitude reduction + c_t (4 rows/warp, stcs stores)
    {
        const int warps = B_ * NS / 4;
        dim3 grid(warps / 8);
        s_update_kernel<<<grid, 256>>>(S_i, S_out, u_a, b_a, t_ptr);
    }
    // 3) output GEMM + final elementwise (R11-exact BM=32 shape)
    {
        dim3 grid(NS / 64, B_ / 32);           // (4, 64) = 256 CTAs
        gemm3_kernel<<<grid, 256>>>(W_o, b_o, h_out);
    }
}

// round 15
// speedup vs baseline: 1.3116x; 1.0277x over previous
#include <cuda_runtime.h>
#include <cuda_bf16.h>
#include <math.h>
#include <stdint.h>

#define B_   2048
#define DIN  512
#define NS   256
#define NF   64
#define KTOT 768     // DIN + NS
#define NTOT 1088    // 256 + 64 + 256 + 256 + 256

// ---- scratch (device globals; no runtime allocation) ----
__device__ float g_fste [B_ * NS];
__device__ float g_ffreq[B_ * NF];
__device__ float g_id   [B_ * NS];
__device__ float g_cw   [B_ * NS];
__device__ float g_opre [B_ * NS];
__device__ float g_ct   [B_ * NS];
__device__ __nv_bfloat16 g_Ahi[(size_t)B_ * KTOT];
__device__ __nv_bfloat16 g_Alo[(size_t)B_ * KTOT];
__device__ __nv_bfloat16 g_Whi[(size_t)NTOT * KTOT];
__device__ __nv_bfloat16 g_Wlo[(size_t)NTOT * KTOT];

__device__ __forceinline__ float sigmoidf_(float z) { return 1.0f / (1.0f + __expf(-z)); }

__device__ __forceinline__ uint32_t smem_u32(const void* p) {
    uint32_t a;
    asm("{ .reg .u64 t; cvta.to.shared.u64 t, %1; cvt.u32.u64 %0, t; }" : "=r"(a) : "l"(p));
    return a;
}

// 64B-row swizzle: XOR 16B-chunk bits[5:4] with bits[8:7] (row>>1)
#define SW64(x) ((x) ^ (((x) >> 3) & 0x30))

#define CP16(dst, src) \
    asm volatile("cp.async.cg.shared.global [%0], [%1], 16;" :: "r"(dst), "l"(src))
#define CP_COMMIT() asm volatile("cp.async.commit_group;" ::: "memory")
#define CP_WAIT1()  asm volatile("cp.async.wait_group 1;" ::: "memory")

__device__ __forceinline__ void ldsm4(uint32_t r[4], uint32_t addr) {
    asm volatile("ldmatrix.sync.aligned.m8n8.x4.shared.b16 {%0,%1,%2,%3}, [%4];"
        : "=r"(r[0]), "=r"(r[1]), "=r"(r[2]), "=r"(r[3]) : "r"(addr));
}
__device__ __forceinline__ void mma_bf16(float c[4], const uint32_t a[4], const uint32_t b[2]) {
    asm volatile("mma.sync.aligned.m16n8k16.row.col.f32.bf16.bf16.f32 "
        "{%0,%1,%2,%3}, {%4,%5,%6,%7}, {%8,%9}, {%0,%1,%2,%3};"
        : "+f"(c[0]), "+f"(c[1]), "+f"(c[2]), "+f"(c[3])
        : "r"(a[0]), "r"(a[1]), "r"(a[2]), "r"(a[3]), "r"(b[0]), "r"(b[1]));
}

// ============================================================================
// Merged pack kernel: blocks [0, 1536) pack x_h, blocks [1536, 2352) pack W.
// ============================================================================
#define PACKX_BLOCKS ((B_ * KTOT) / (256 * 4))     // 1536
#define PACKW_BLOCKS ((KTOT / 32) * (NTOT / 32))   // 24 * 34 = 816

__global__ __launch_bounds__(256)
void pack_all_kernel(const float* __restrict__ x, const float* __restrict__ h,
                     const float* __restrict__ Wf, const float* __restrict__ Wff,
                     const float* __restrict__ Wi, const float* __restrict__ Wc,
                     const float* __restrict__ Wo)
{
    const int tid = threadIdx.x;
    if (blockIdx.x < PACKX_BLOCKS) {
        const int i = (blockIdx.x * 256 + tid) * 4;
        const int b = i / KTOT;
        const int k = i % KTOT;
        float4 v;
        if (k < DIN) v = *(const float4*)(x + (size_t)b * DIN + k);
        else         v = *(const float4*)(h + (size_t)b * NS + (k - DIN));
        float a[4] = {v.x, v.y, v.z, v.w};
#pragma unroll
        for (int j = 0; j < 4; j++) {
            __nv_bfloat16 hi = __float2bfloat16(a[j]);
            __nv_bfloat16 lo = __float2bfloat16(a[j] - __bfloat162float(hi));
            g_Ahi[(size_t)i + j] = hi;
            g_Alo[(size_t)i + j] = lo;
        }
    } else {
        __shared__ float tile[32][33];
        const int wb = blockIdx.x - PACKX_BLOCKS;
        const int k0 = (wb % (KTOT / 32)) * 32;
        const int n0 = (wb / (KTOT / 32)) * 32;
        const int tx = tid & 31;
        const int tyy = tid >> 5;      // 0..7
        for (int r = tyy; r < 32; r += 8) {
            const int k = k0 + r;
            const int n = n0 + tx;
            float v;
            if      (n < 256) v = Wf [(size_t)k * 256 + n];
            else if (n < 320) v = Wff[(size_t)k * 64  + (n - 256)];
            else if (n < 576) v = Wi [(size_t)k * 256 + (n - 320)];
            else if (n < 832) v = Wc [(size_t)k * 256 + (n - 576)];
            else              v = Wo [(size_t)k * 256 + (n - 832)];
            tile[r][tx] = v;
        }
        __syncthreads();
        for (int r = tyy; r < 32; r += 8) {
            const int n = n0 + r;
            const int k = k0 + tx;
            const float v = tile[tx][r];
            const __nv_bfloat16 hi = __float2bfloat16(v);
            g_Whi[(size_t)n * KTOT + k] = hi;
            g_Wlo[(size_t)n * KTOT + k] = __float2bfloat16(v - __bfloat162float(hi));
        }
    }
}

// ============================================================================
// Kernel 1: bf16x3 gate GEMM via mma.sync (HMMA). BM=64 BN=64 BK=32,
// 16x32 warp tile (low reg pressure -> 3 CTAs/SM, 24 warps/SM),
// 3-stage cp.async pipeline, ldmatrix + SW64 swizzle, fused segment epilogue.
// Stage layout: Ahi@0 4K | Alo@4096 | Bhi@8192 | Blo@12288 (16K/stage).
// ============================================================================
#define STAGE_BYTES 16384
#define NKSTEP (KTOT / 32)           // 24
#define MMA_SMEM_TOTAL (3 * STAGE_BYTES)

__global__ __launch_bounds__(256, 3)
void gemm1_mma_kernel(const float* __restrict__ b_fste, const float* __restrict__ b_ffreq,
                      const float* __restrict__ b_i, const float* __restrict__ b_c)
{
    extern __shared__ char smem[];
    const uint32_t sb = smem_u32(smem);
    const int tid = threadIdx.x;
    const int wid = tid >> 5;
    const int l   = tid & 31;
    const int wm  = wid >> 1;     // 0..3  (16-row slab)
    const int wn  = wid & 1;      // 0..1  (32-col slab)
    const int m0 = blockIdx.y * 64;
    const int n0 = blockIdx.x * 64;

    const int rA = (l & 7) + ((l >> 3) & 1) * 8;   // A: m within m16 atom
    const int kA = ((l >> 4) & 1) * 16;            // A: k-half byte offset
    const int rB = (l & 7) + ((l >> 4) & 1) * 8;   // B: n within 16-row pair
    const int kB = ((l >> 3) & 1) * 16;            // B: k-half byte offset

    const int aRow = tid >> 2;           // 0..63
    const int aKc  = tid & 3;
    const int bRow = tid >> 2;           // 0..63

    float acc[4][4];                     // na x 4
#pragma unroll
    for (int j = 0; j < 4; j++)
#pragma unroll
        for (int q = 0; q < 4; q++) acc[j][q] = 0.0f;

#define LOAD_STAGE(ks_) do { \
    const int k0_ = (ks_) * 32; \
    const uint32_t st_ = sb + ((ks_) % 3) * STAGE_BYTES; \
    { \
        const uint32_t d = st_ + SW64(aRow * 64 + aKc * 16); \
        CP16(d,        g_Ahi + (size_t)(m0 + aRow) * KTOT + k0_ + aKc * 8); \
        CP16(d + 4096, g_Alo + (size_t)(m0 + aRow) * KTOT + k0_ + aKc * 8); \
    } \
    { \
        const uint32_t d = st_ + 8192 + SW64(bRow * 64 + aKc * 16); \
        CP16(d,        g_Whi + (size_t)(n0 + bRow) * KTOT + k0_ + aKc * 8); \
        CP16(d + 4096, g_Wlo + (size_t)(n0 + bRow) * KTOT + k0_ + aKc * 8); \
    } \
} while (0)

    LOAD_STAGE(0); CP_COMMIT();
    LOAD_STAGE(1); CP_COMMIT();

    for (int ks = 0; ks < NKSTEP; ks++) {
        CP_WAIT1();
        __syncthreads();
        if (ks + 2 < NKSTEP) LOAD_STAGE(ks + 2);
        CP_COMMIT();

        const uint32_t st = sb + (ks % 3) * STAGE_BYTES;
#pragma unroll
        for (int k16 = 0; k16 < 2; k16++) {
            uint32_t ah[4], al[4], bh[4][2], bl[4][2];
            {
                const uint32_t off = SW64((wm * 16 + rA) * 64 + kA + k16 * 32);
                ldsm4(ah, st + off);
                ldsm4(al, st + 4096 + off);
            }
#pragma unroll
            for (int p = 0; p < 2; p++) {
                const uint32_t off = 8192 + SW64((wn * 32 + p * 16 + rB) * 64 + kB + k16 * 32);
                uint32_t q[4];
                ldsm4(q, st + off);
                bh[2 * p][0] = q[0]; bh[2 * p][1] = q[1];
                bh[2 * p + 1][0] = q[2]; bh[2 * p + 1][1] = q[3];
                ldsm4(q, st + 4096 + off);
                bl[2 * p][0] = q[0]; bl[2 * p][1] = q[1];
                bl[2 * p + 1][0] = q[2]; bl[2 * p + 1][1] = q[3];
            }
#pragma unroll
            for (int na = 0; na < 4; na++) {
                mma_bf16(acc[na], ah, bh[na]);
                mma_bf16(acc[na], ah, bl[na]);
                mma_bf16(acc[na], al, bh[na]);
            }
        }
    }

    // --- fused segment epilogue (block entirely within one segment) ---
    float* dst; const float* bias; int colw, coloff, act;
    if      (n0 < 256) { dst = g_fste;  bias = b_fste;  colw = NS; coloff = n0;       act = 0; }
    else if (n0 < 320) { dst = g_ffreq; bias = b_ffreq; colw = NF; coloff = n0 - 256; act = 0; }
    else if (n0 < 576) { dst = g_id;    bias = b_i;     colw = NS; coloff = n0 - 320; act = 0; }
    else if (n0 < 832) { dst = g_cw;    bias = b_c;     colw = NS; coloff = n0 - 576; act = 1; }
    else               { dst = g_opre;  bias = b_fste;  colw = NS; coloff = n0 - 832; act = 2; }

#pragma unroll
    for (int half = 0; half < 2; half++) {
        const int gm = m0 + wm * 16 + (l >> 2) + half * 8;
#pragma unroll
        for (int na = 0; na < 4; na++) {
            const int col = wn * 32 + na * 8 + (l & 3) * 2;
            float v0 = acc[na][half * 2 + 0];
            float v1 = acc[na][half * 2 + 1];
            if (act == 0) {
                v0 = sigmoidf_(v0 + bias[coloff + col]);
                v1 = sigmoidf_(v1 + bias[coloff + col + 1]);
            } else if (act == 1) {
                v0 = tanhf(v0 + bias[coloff + col]);
                v1 = tanhf(v1 + bias[coloff + col + 1]);
            }
            *(float2*)(dst + (size_t)gm * colw + coloff + col) = make_float2(v0, v1);
        }
    }
#undef LOAD_STAGE
}

// ============================================================================
// Kernel 2: fused S update + amplitude reduction + c_t. (R14 exact)
// 4 rows/warp, MLP=8 loads; __stcs stores.
// ============================================================================
__global__ __launch_bounds__(256)
void s_update_kernel(const float* __restrict__ S_in, float* __restrict__ S_out,
                     const float* __restrict__ u_a, const float* __restrict__ b_a,
                     const int* __restrict__ t_ptr)
{
    const uint32_t warp = (blockIdx.x * 256u + threadIdx.x) >> 5;   // [0, B_*NS/4)
    const uint32_t lane = threadIdx.x & 31u;
    const uint32_t r0 = warp << 2;
    const uint32_t b  = r0 >> 8;
    const uint32_t i0 = r0 & 255u;
    const uint32_t j0 = lane << 1;

    const uint32_t base00 = (b << 15) + (i0 << 6) + j0;
    float2 sv[4][2];
#pragma unroll
    for (int q = 0; q < 4; q++) {
        sv[q][0] = *(const float2*)(S_in + base00 + (uint32_t)(q << 6));
        sv[q][1] = *(const float2*)(S_in + base00 + (uint32_t)(q << 6) + (1u << 14));
    }

    float fs[4], ic[4];
#pragma unroll
    for (int q = 0; q < 4; q++) {
        fs[q] = g_fste[r0 + q];
        ic[q] = g_id[r0 + q] * g_cw[r0 + q];
    }
    const float2 ff = *(const float2*)(g_ffreq + (b << 6) + j0);

    const int t = *t_ptr;
    const int m0 = ((int)j0 * t) & 63;
    const int m1 = ((int)(j0 + 1) * t) & 63;
    const float C = 0.098174770424681038798f;  // 2*pi/64
    float s0a, c0a, s1a, c1a;
    __sincosf((float)m0 * C, &s0a, &c0a);
    __sincosf((float)m1 * C, &s1a, &c1a);

    const float2 ua = *(const float2*)(u_a + j0);

    float accv[4];
#pragma unroll
    for (int q = 0; q < 4; q++) {
        const float f0 = fs[q] * ff.x;
        const float f1 = fs[q] * ff.y;
        float2 sn0, sn1;
        sn0.x = sv[q][0].x * f0 + ic[q] * s0a;
        sn0.y = sv[q][0].y * f1 + ic[q] * s1a;
        sn1.x = sv[q][1].x * f0 + ic[q] * c0a;
        sn1.y = sv[q][1].y * f1 + ic[q] * c1a;
        __stcs((float2*)(S_out + base00 + (uint32_t)(q << 6)), sn0);
        __stcs((float2*)(S_out + base00 + (uint32_t)(q << 6) + (1u << 14)), sn1);
        accv[q] = sqrtf(sn0.x * sn0.x + sn1.x * sn1.x) * ua.x
                + sqrtf(sn0.y * sn0.y + sn1.y * sn1.y) * ua.y;
    }

#pragma unroll
    for (int off = 16; off; off >>= 1) {
#pragma unroll
        for (int q = 0; q < 4; q++)
            accv[q] += __shfl_xor_sync(0xffffffff, accv[q], off);
    }

    if (lane == 0) {
#pragma unroll
        for (int q = 0; q < 4; q++)
            g_ct[r0 + q] = sigmoidf_(accv[q] + b_a[i0 + q]);
    }
}

// ============================================================================
// Kernel 3: output GEMM, register-double-buffered smem pipeline. (R11 exact)
// BM=32 BN=64 BK=32 TM=2 TN=4, 256 thr, grid (4,64)=256 CTAs, 8 K-iters.
// ============================================================================
__global__ __launch_bounds__(256)
void gemm3_kernel(const float* __restrict__ W_o, const float* __restrict__ b_o,
                  float* __restrict__ h_out)
{
    constexpr int BM = 32, BN = 64, BK = 32, TM = 2, TN = 4;
    constexpr int NIT = NS / BK;   // 8
    __shared__ float As[2][BK][BM + 1];
    __shared__ float Bs[2][BK][BN + 4];

    const int tid = threadIdx.x;
    const int m0 = blockIdx.y * BM;
    const int n0 = blockIdx.x * BN;
    const int tx = tid & 15;     // 16 cols * TN=4 -> 64
    const int ty = tid >> 4;     // 16 rows * TM=2 -> 32

    const float* Wc = W_o + (size_t)KTOT * 256;

    const int ar = tid >> 3;          // 0..31 (A row)
    const int ac = (tid & 7) * 4;     // 0..28 (A k-col, float4)
    const int br = tid >> 4;          // 0..15 (B k-row; +16 for rep)
    const int bc = (tid & 15) * 4;    // 0..60 (B n-col, float4)

    float acc[TM][TN];
#pragma unroll
    for (int i = 0; i < TM; i++)
#pragma unroll
        for (int j = 0; j < TN; j++) acc[i][j] = 0.0f;

    float4 pa, pb0, pb1;

    pa  = *(const float4*)(g_ct + (size_t)(m0 + ar) * NS + ac);
    pb0 = *(const float4*)(Wc + (size_t)br * 256 + n0 + bc);
    pb1 = *(const float4*)(Wc + (size_t)(br + 16) * 256 + n0 + bc);
    As[0][ac + 0][ar] = pa.x; As[0][ac + 1][ar] = pa.y;
    As[0][ac + 2][ar] = pa.z; As[0][ac + 3][ar] = pa.w;
    Bs[0][br][bc + 0] = pb0.x; Bs[0][br][bc + 1] = pb0.y;
    Bs[0][br][bc + 2] = pb0.z; Bs[0][br][bc + 3] = pb0.w;
    Bs[0][br + 16][bc + 0] = pb1.x; Bs[0][br + 16][bc + 1] = pb1.y;
    Bs[0][br + 16][bc + 2] = pb1.z; Bs[0][br + 16][bc + 3] = pb1.w;
    __syncthreads();

    for (int it = 0; it < NIT; it++) {
        const int s = it & 1;
        if (it + 1 < NIT) {
            const int k0 = (it + 1) * BK;
            pa  = *(const float4*)(g_ct + (size_t)(m0 + ar) * NS + k0 + ac);
            pb0 = *(const float4*)(Wc + (size_t)(k0 + br) * 256 + n0 + bc);
            pb1 = *(const float4*)(Wc + (size_t)(k0 + br + 16) * 256 + n0 + bc);
        }

#pragma unroll
        for (int kk = 0; kk < BK; kk++) {
            float ra[TM], rb[TN];
#pragma unroll
            for (int i = 0; i < TM; i++) ra[i] = As[s][kk][ty * TM + i];
#pragma unroll
            for (int j = 0; j < TN; j++) rb[j] = Bs[s][kk][tx * TN + j];
#pragma unroll
            for (int i = 0; i < TM; i++)
#pragma unroll
                for (int j = 0; j < TN; j++) acc[i][j] = fmaf(ra[i], rb[j], acc[i][j]);
        }

        if (it + 1 < NIT) {
            const int d = s ^ 1;
            As[d][ac + 0][ar] = pa.x; As[d][ac + 1][ar] = pa.y;
            As[d][ac + 2][ar] = pa.z; As[d][ac + 3][ar] = pa.w;
            Bs[d][br][bc + 0] = pb0.x; Bs[d][br][bc + 1] = pb0.y;
            Bs[d][br][bc + 2] = pb0.z; Bs[d][br][bc + 3] = pb0.w;
            Bs[d][br + 16][bc + 0] = pb1.x; Bs[d][br + 16][bc + 1] = pb1.y;
            Bs[d][br + 16][bc + 2] = pb1.z; Bs[d][br + 16][bc + 3] = pb1.w;
            __syncthreads();
        }
    }

#pragma unroll
    for (int i = 0; i < TM; i++) {
        const int gm = m0 + ty * TM + i;
#pragma unroll
        for (int j = 0; j < TN; j++) {
            const int gn = n0 + tx * TN + j;
            const float z = acc[i][j] + g_opre[(size_t)gm * NS + gn] + b_o[gn];
            const float ct = g_ct[(size_t)gm * NS + gn];
            h_out[(size_t)gm * NS + gn] = sigmoidf_(z) * ct;
        }
    }
}

// ============================================================================
extern "C" void kernel_launch(void* const* d_in, const int* in_sizes, int n_in,
                              void* d_out, int out_size)
{
    const float* x_i     = (const float*)d_in[0];
    const float* h_i     = (const float*)d_in[1];
    const float* S_i     = (const float*)d_in[2];
    const float* W_fste  = (const float*)d_in[3];
    const float* b_fste  = (const float*)d_in[4];
    const float* W_ffreq = (const float*)d_in[5];
    const float* b_ffreq = (const float*)d_in[6];
    const float* W_i     = (const float*)d_in[7];
    const float* b_i     = (const float*)d_in[8];
    const float* W_c     = (const float*)d_in[9];
    const float* b_c     = (const float*)d_in[10];
    const float* u_a     = (const float*)d_in[11];
    const float* b_a     = (const float*)d_in[12];
    const float* W_o     = (const float*)d_in[13];
    const float* b_o     = (const float*)d_in[14];
    const int*   t_ptr   = (const int*)d_in[15];

    float* out = (float*)d_out;
    float* h_out = out;                        // [B, NS]
    float* S_out = out + (size_t)B_ * NS;      // [B, 2, NS, NF]

    cudaFuncSetAttribute(gemm1_mma_kernel, cudaFuncAttributeMaxDynamicSharedMemorySize,
                         MMA_SMEM_TOTAL);

    // 0) pack operands to bf16 hi/lo (single launch)
    pack_all_kernel<<<PACKX_BLOCKS + PACKW_BLOCKS, 256>>>(x_i, h_i, W_fste, W_ffreq,
                                                          W_i, W_c, W_o);
    // 1) gate GEMM on HMMA tensor cores (bf16x3, 16x32 warp tile, 3 CTAs/SM)
    {
        dim3 grid(NTOT / 64, B_ / 64);         // (17, 32) = 544 CTAs
        gemm1_mma_kernel<<<grid, 256, MMA_SMEM_TOTAL>>>(b_fste, b_ffreq, b_i, b_c);
    }
    // 2) fused S update + amplitude reduction + c_t (4 rows/warp, stcs stores)
    {
        const int warps = B_ * NS / 4;
        dim3 grid(warps / 8);
        s_update_kernel<<<grid, 256>>>(S_i, S_out, u_a, b_a, t_ptr);
    }
    // 3) output GEMM + final elementwise (R11-exact BM=32 shape)
    {
        dim3 grid(NS / 64, B_ / 32);           // (4, 64) = 256 CTAs
        gemm3_kernel<<<grid, 256>>>(W_o, b_o, h_out);
    }
}

// round 16
// speedup vs baseline: 1.4030x; 1.0696x over previous
#include <cuda_runtime.h>
#include <cuda_bf16.h>
#include <math.h>
#include <stdint.h>

#define B_   2048
#define DIN  512
#define NS   256
#define NF   64
#define KTOT 768     // DIN + NS
#define NTOT 1088    // 256 + 64 + 256 + 256 + 256

// ---- scratch (device globals; no runtime allocation) ----
__device__ float g_fste [B_ * NS];
__device__ float g_ffreq[B_ * NF];
__device__ float g_id   [B_ * NS];
__device__ float g_cw   [B_ * NS];
__device__ float g_opre [B_ * NS];
__device__ float g_ct   [B_ * NS];
__device__ __nv_bfloat16 g_Ahi[(size_t)B_ * KTOT];
__device__ __nv_bfloat16 g_Alo[(size_t)B_ * KTOT];
__device__ __nv_bfloat16 g_Whi[(size_t)NTOT * KTOT];
__device__ __nv_bfloat16 g_Wlo[(size_t)NTOT * KTOT];
__device__ __nv_bfloat16 g_Cthi[(size_t)B_ * NS];
__device__ __nv_bfloat16 g_Ctlo[(size_t)B_ * NS];
__device__ __nv_bfloat16 g_Wohi[(size_t)NS * NS];
__device__ __nv_bfloat16 g_Wolo[(size_t)NS * NS];

__device__ __forceinline__ float sigmoidf_(float z) { return 1.0f / (1.0f + __expf(-z)); }

__device__ __forceinline__ uint32_t smem_u32(const void* p) {
    uint32_t a;
    asm("{ .reg .u64 t; cvta.to.shared.u64 t, %1; cvt.u32.u64 %0, t; }" : "=r"(a) : "l"(p));
    return a;
}

// 64B-row swizzle: XOR 16B-chunk bits[5:4] with bits[8:7] (row>>1)
#define SW64(x) ((x) ^ (((x) >> 3) & 0x30))

#define CP16(dst, src) \
    asm volatile("cp.async.cg.shared.global [%0], [%1], 16;" :: "r"(dst), "l"(src))
#define CP_COMMIT() asm volatile("cp.async.commit_group;" ::: "memory")
#define CP_WAIT1()  asm volatile("cp.async.wait_group 1;" ::: "memory")

__device__ __forceinline__ void ldsm4(uint32_t r[4], uint32_t addr) {
    asm volatile("ldmatrix.sync.aligned.m8n8.x4.shared.b16 {%0,%1,%2,%3}, [%4];"
        : "=r"(r[0]), "=r"(r[1]), "=r"(r[2]), "=r"(r[3]) : "r"(addr));
}
__device__ __forceinline__ void mma_bf16(float c[4], const uint32_t a[4], const uint32_t b[2]) {
    asm volatile("mma.sync.aligned.m16n8k16.row.col.f32.bf16.bf16.f32 "
        "{%0,%1,%2,%3}, {%4,%5,%6,%7}, {%8,%9}, {%0,%1,%2,%3};"
        : "+f"(c[0]), "+f"(c[1]), "+f"(c[2]), "+f"(c[3])
        : "r"(a[0]), "r"(a[1]), "r"(a[2]), "r"(a[3]), "r"(b[0]), "r"(b[1]));
}

// ============================================================================
// Merged pack kernel: [0,1536) pack x_h; [1536,2352) pack W (gate);
// [2352,2416) pack W_o rows 768..1023 transposed -> g_Wohi/lo [n][k].
// ============================================================================
#define PACKX_BLOCKS ((B_ * KTOT) / (256 * 4))     // 1536
#define PACKW_BLOCKS ((KTOT / 32) * (NTOT / 32))   // 816
#define PACKW2_BLOCKS ((NS / 32) * (NS / 32))      // 64

__global__ __launch_bounds__(256)
void pack_all_kernel(const float* __restrict__ x, const float* __restrict__ h,
                     const float* __restrict__ Wf, const float* __restrict__ Wff,
                     const float* __restrict__ Wi, const float* __restrict__ Wc,
                     const float* __restrict__ Wo)
{
    const int tid = threadIdx.x;
    if (blockIdx.x < PACKX_BLOCKS) {
        const int i = (blockIdx.x * 256 + tid) * 4;
        const int b = i / KTOT;
        const int k = i % KTOT;
        float4 v;
        if (k < DIN) v = *(const float4*)(x + (size_t)b * DIN + k);
        else         v = *(const float4*)(h + (size_t)b * NS + (k - DIN));
        float a[4] = {v.x, v.y, v.z, v.w};
#pragma unroll
        for (int j = 0; j < 4; j++) {
            __nv_bfloat16 hi = __float2bfloat16(a[j]);
            __nv_bfloat16 lo = __float2bfloat16(a[j] - __bfloat162float(hi));
            g_Ahi[(size_t)i + j] = hi;
            g_Alo[(size_t)i + j] = lo;
        }
    } else if (blockIdx.x < PACKX_BLOCKS + PACKW_BLOCKS) {
        __shared__ float tile[32][33];
        const int wb = blockIdx.x - PACKX_BLOCKS;
        const int k0 = (wb % (KTOT / 32)) * 32;
        const int n0 = (wb / (KTOT / 32)) * 32;
        const int tx = tid & 31;
        const int tyy = tid >> 5;      // 0..7
        for (int r = tyy; r < 32; r += 8) {
            const int k = k0 + r;
            const int n = n0 + tx;
            float v;
            if      (n < 256) v = Wf [(size_t)k * 256 + n];
            else if (n < 320) v = Wff[(size_t)k * 64  + (n - 256)];
            else if (n < 576) v = Wi [(size_t)k * 256 + (n - 320)];
            else if (n < 832) v = Wc [(size_t)k * 256 + (n - 576)];
            else              v = Wo [(size_t)k * 256 + (n - 832)];
            tile[r][tx] = v;
        }
        __syncthreads();
        for (int r = tyy; r < 32; r += 8) {
            const int n = n0 + r;
            const int k = k0 + tx;
            const float v = tile[tx][r];
            const __nv_bfloat16 hi = __float2bfloat16(v);
            g_Whi[(size_t)n * KTOT + k] = hi;
            g_Wlo[(size_t)n * KTOT + k] = __float2bfloat16(v - __bfloat162float(hi));
        }
    } else {
        // pack W_o rows [768, 1024) transposed: g_Wo*[n][k] = Wo[(768+k)][n]
        __shared__ float tile[32][33];
        const int wb = blockIdx.x - PACKX_BLOCKS - PACKW_BLOCKS;
        const int k0 = (wb % (NS / 32)) * 32;
        const int n0 = (wb / (NS / 32)) * 32;
        const int tx = tid & 31;
        const int tyy = tid >> 5;
        for (int r = tyy; r < 32; r += 8) {
            tile[r][tx] = Wo[(size_t)(KTOT + k0 + r) * 256 + n0 + tx];
        }
        __syncthreads();
        for (int r = tyy; r < 32; r += 8) {
            const int n = n0 + r;
            const int k = k0 + tx;
            const float v = tile[tx][r];
            const __nv_bfloat16 hi = __float2bfloat16(v);
            g_Wohi[(size_t)n * NS + k] = hi;
            g_Wolo[(size_t)n * NS + k] = __float2bfloat16(v - __bfloat162float(hi));
        }
    }
}

// ============================================================================
// Kernel 1: bf16x3 gate GEMM via mma.sync (HMMA). BM=64 BN=64 BK=32,
// 16x32 warp tile, 3 CTAs/SM, 3-stage cp.async, SW64 swizzle. (R15 exact)
// ============================================================================
#define STAGE_BYTES 16384
#define NKSTEP (KTOT / 32)           // 24
#define MMA_SMEM_TOTAL (3 * STAGE_BYTES)

__global__ __launch_bounds__(256, 3)
void gemm1_mma_kernel(const float* __restrict__ b_fste, const float* __restrict__ b_ffreq,
                      const float* __restrict__ b_i, const float* __restrict__ b_c)
{
    extern __shared__ char smem[];
    const uint32_t sb = smem_u32(smem);
    const int tid = threadIdx.x;
    const int wid = tid >> 5;
    const int l   = tid & 31;
    const int wm  = wid >> 1;     // 0..3  (16-row slab)
    const int wn  = wid & 1;      // 0..1  (32-col slab)
    const int m0 = blockIdx.y * 64;
    const int n0 = blockIdx.x * 64;

    const int rA = (l & 7) + ((l >> 3) & 1) * 8;
    const int kA = ((l >> 4) & 1) * 16;
    const int rB = (l & 7) + ((l >> 4) & 1) * 8;
    const int kB = ((l >> 3) & 1) * 16;

    const int aRow = tid >> 2;           // 0..63
    const int aKc  = tid & 3;
    const int bRow = tid >> 2;           // 0..63

    float acc[4][4];
#pragma unroll
    for (int j = 0; j < 4; j++)
#pragma unroll
        for (int q = 0; q < 4; q++) acc[j][q] = 0.0f;

#define LOAD_STAGE(ks_) do { \
    const int k0_ = (ks_) * 32; \
    const uint32_t st_ = sb + ((ks_) % 3) * STAGE_BYTES; \
    { \
        const uint32_t d = st_ + SW64(aRow * 64 + aKc * 16); \
        CP16(d,        g_Ahi + (size_t)(m0 + aRow) * KTOT + k0_ + aKc * 8); \
        CP16(d + 4096, g_Alo + (size_t)(m0 + aRow) * KTOT + k0_ + aKc * 8); \
    } \
    { \
        const uint32_t d = st_ + 8192 + SW64(bRow * 64 + aKc * 16); \
        CP16(d,        g_Whi + (size_t)(n0 + bRow) * KTOT + k0_ + aKc * 8); \
        CP16(d + 4096, g_Wlo + (size_t)(n0 + bRow) * KTOT + k0_ + aKc * 8); \
    } \
} while (0)

    LOAD_STAGE(0); CP_COMMIT();
    LOAD_STAGE(1); CP_COMMIT();

    for (int ks = 0; ks < NKSTEP; ks++) {
        CP_WAIT1();
        __syncthreads();
        if (ks + 2 < NKSTEP) LOAD_STAGE(ks + 2);
        CP_COMMIT();

        const uint32_t st = sb + (ks % 3) * STAGE_BYTES;
#pragma unroll
        for (int k16 = 0; k16 < 2; k16++) {
            uint32_t ah[4], al[4], bh[4][2], bl[4][2];
            {
                const uint32_t off = SW64((wm * 16 + rA) * 64 + kA + k16 * 32);
                ldsm4(ah, st + off);
                ldsm4(al, st + 4096 + off);
            }
#pragma unroll
            for (int p = 0; p < 2; p++) {
                const uint32_t off = 8192 + SW64((wn * 32 + p * 16 + rB) * 64 + kB + k16 * 32);
                uint32_t q[4];
                ldsm4(q, st + off);
                bh[2 * p][0] = q[0]; bh[2 * p][1] = q[1];
                bh[2 * p + 1][0] = q[2]; bh[2 * p + 1][1] = q[3];
                ldsm4(q, st + 4096 + off);
                bl[2 * p][0] = q[0]; bl[2 * p][1] = q[1];
                bl[2 * p + 1][0] = q[2]; bl[2 * p + 1][1] = q[3];
            }
#pragma unroll
            for (int na = 0; na < 4; na++) {
                mma_bf16(acc[na], ah, bh[na]);
                mma_bf16(acc[na], ah, bl[na]);
                mma_bf16(acc[na], al, bh[na]);
            }
        }
    }

    float* dst; const float* bias; int colw, coloff, act;
    if      (n0 < 256) { dst = g_fste;  bias = b_fste;  colw = NS; coloff = n0;       act = 0; }
    else if (n0 < 320) { dst = g_ffreq; bias = b_ffreq; colw = NF; coloff = n0 - 256; act = 0; }
    else if (n0 < 576) { dst = g_id;    bias = b_i;     colw = NS; coloff = n0 - 320; act = 0; }
    else if (n0 < 832) { dst = g_cw;    bias = b_c;     colw = NS; coloff = n0 - 576; act = 1; }
    else               { dst = g_opre;  bias = b_fste;  colw = NS; coloff = n0 - 832; act = 2; }

#pragma unroll
    for (int half = 0; half < 2; half++) {
        const int gm = m0 + wm * 16 + (l >> 2) + half * 8;
#pragma unroll
        for (int na = 0; na < 4; na++) {
            const int col = wn * 32 + na * 8 + (l & 3) * 2;
            float v0 = acc[na][half * 2 + 0];
            float v1 = acc[na][half * 2 + 1];
            if (act == 0) {
                v0 = sigmoidf_(v0 + bias[coloff + col]);
                v1 = sigmoidf_(v1 + bias[coloff + col + 1]);
            } else if (act == 1) {
                v0 = tanhf(v0 + bias[coloff + col]);
                v1 = tanhf(v1 + bias[coloff + col + 1]);
            }
            *(float2*)(dst + (size_t)gm * colw + coloff + col) = make_float2(v0, v1);
        }
    }
#undef LOAD_STAGE
}

// ============================================================================
// Kernel 2: fused S update + amplitude reduction + c_t.
// 4 rows/warp, MLP=8, __stcs stores; also emits c_t as bf16 hi/lo.
// ============================================================================
__global__ __launch_bounds__(256)
void s_update_kernel(const float* __restrict__ S_in, float* __restrict__ S_out,
                     const float* __restrict__ u_a, const float* __restrict__ b_a,
                     const int* __restrict__ t_ptr)
{
    const uint32_t warp = (blockIdx.x * 256u + threadIdx.x) >> 5;
    const uint32_t lane = threadIdx.x & 31u;
    const uint32_t r0 = warp << 2;
    const uint32_t b  = r0 >> 8;
    const uint32_t i0 = r0 & 255u;
    const uint32_t j0 = lane << 1;

    const uint32_t base00 = (b << 15) + (i0 << 6) + j0;
    float2 sv[4][2];
#pragma unroll
    for (int q = 0; q < 4; q++) {
        sv[q][0] = *(const float2*)(S_in + base00 + (uint32_t)(q << 6));
        sv[q][1] = *(const float2*)(S_in + base00 + (uint32_t)(q << 6) + (1u << 14));
    }

    float fs[4], ic[4];
#pragma unroll
    for (int q = 0; q < 4; q++) {
        fs[q] = g_fste[r0 + q];
        ic[q] = g_id[r0 + q] * g_cw[r0 + q];
    }
    const float2 ff = *(const float2*)(g_ffreq + (b << 6) + j0);

    const int t = *t_ptr;
    const int m0 = ((int)j0 * t) & 63;
    const int m1 = ((int)(j0 + 1) * t) & 63;
    const float C = 0.098174770424681038798f;  // 2*pi/64
    float s0a, c0a, s1a, c1a;
    __sincosf((float)m0 * C, &s0a, &c0a);
    __sincosf((float)m1 * C, &s1a, &c1a);

    const float2 ua = *(const float2*)(u_a + j0);

    float accv[4];
#pragma unroll
    for (int q = 0; q < 4; q++) {
        const float f0 = fs[q] * ff.x;
        const float f1 = fs[q] * ff.y;
        float2 sn0, sn1;
        sn0.x = sv[q][0].x * f0 + ic[q] * s0a;
        sn0.y = sv[q][0].y * f1 + ic[q] * s1a;
        sn1.x = sv[q][1].x * f0 + ic[q] * c0a;
        sn1.y = sv[q][1].y * f1 + ic[q] * c1a;
        __stcs((float2*)(S_out + base00 + (uint32_t)(q << 6)), sn0);
        __stcs((float2*)(S_out + base00 + (uint32_t)(q << 6) + (1u << 14)), sn1);
        accv[q] = sqrtf(sn0.x * sn0.x + sn1.x * sn1.x) * ua.x
                + sqrtf(sn0.y * sn0.y + sn1.y * sn1.y) * ua.y;
    }

#pragma unroll
    for (int off = 16; off; off >>= 1) {
#pragma unroll
        for (int q = 0; q < 4; q++)
            accv[q] += __shfl_xor_sync(0xffffffff, accv[q], off);
    }

    if (lane == 0) {
#pragma unroll
        for (int q = 0; q < 4; q++) {
            const float ct = sigmoidf_(accv[q] + b_a[i0 + q]);
            g_ct[r0 + q] = ct;
            const __nv_bfloat16 hi = __float2bfloat16(ct);
            g_Cthi[r0 + q] = hi;
            g_Ctlo[r0 + q] = __float2bfloat16(ct - __bfloat162float(hi));
        }
    }
}

// ============================================================================
// Kernel 3: output GEMM via HMMA bf16x3, same machinery as gemm1.
// M=2048 N=256 K=256; BM=64 BN=64 BK=32, 16x32 warp tile, 3-stage pipeline.
// Grid (4, 32) = 128 CTAs (single wave at 3 CTAs/SM).
// Epilogue: h = sigmoid(acc + opre + b_o) * ct.
// ============================================================================
#define NKSTEP3 (NS / 32)            // 8

__global__ __launch_bounds__(256, 3)
void gemm3_mma_kernel(const float* __restrict__ b_o, float* __restrict__ h_out)
{
    extern __shared__ char smem[];
    const uint32_t sb = smem_u32(smem);
    const int tid = threadIdx.x;
    const int wid = tid >> 5;
    const int l   = tid & 31;
    const int wm  = wid >> 1;     // 0..3
    const int wn  = wid & 1;      // 0..1
    const int m0 = blockIdx.y * 64;
    const int n0 = blockIdx.x * 64;

    const int rA = (l & 7) + ((l >> 3) & 1) * 8;
    const int kA = ((l >> 4) & 1) * 16;
    const int rB = (l & 7) + ((l >> 4) & 1) * 8;
    const int kB = ((l >> 3) & 1) * 16;

    const int aRow = tid >> 2;           // 0..63
    const int aKc  = tid & 3;
    const int bRow = tid >> 2;           // 0..63

    float acc[4][4];
#pragma unroll
    for (int j = 0; j < 4; j++)
#pragma unroll
        for (int q = 0; q < 4; q++) acc[j][q] = 0.0f;

#define LOAD_STAGE3(ks_) do { \
    const int k0_ = (ks_) * 32; \
    const uint32_t st_ = sb + ((ks_) % 3) * STAGE_BYTES; \
    { \
        const uint32_t d = st_ + SW64(aRow * 64 + aKc * 16); \
        CP16(d,        g_Cthi + (size_t)(m0 + aRow) * NS + k0_ + aKc * 8); \
        CP16(d + 4096, g_Ctlo + (size_t)(m0 + aRow) * NS + k0_ + aKc * 8); \
    } \
    { \
        const uint32_t d = st_ + 8192 + SW64(bRow * 64 + aKc * 16); \
        CP16(d,        g_Wohi + (size_t)(n0 + bRow) * NS + k0_ + aKc * 8); \
        CP16(d + 4096, g_Wolo + (size_t)(n0 + bRow) * NS + k0_ + aKc * 8); \
    } \
} while (0)

    LOAD_STAGE3(0); CP_COMMIT();
    LOAD_STAGE3(1); CP_COMMIT();

    for (int ks = 0; ks < NKSTEP3; ks++) {
        CP_WAIT1();
        __syncthreads();
        if (ks + 2 < NKSTEP3) LOAD_STAGE3(ks + 2);
        CP_COMMIT();

        const uint32_t st = sb + (ks % 3) * STAGE_BYTES;
#pragma unroll
        for (int k16 = 0; k16 < 2; k16++) {
            uint32_t ah[4], al[4], bh[4][2], bl[4][2];
            {
                const uint32_t off = SW64((wm * 16 + rA) * 64 + kA + k16 * 32);
                ldsm4(ah, st + off);
                ldsm4(al, st + 4096 + off);
            }
#pragma unroll
            for (int p = 0; p < 2; p++) {
                const uint32_t off = 8192 + SW64((wn * 32 + p * 16 + rB) * 64 + kB + k16 * 32);
                uint32_t q[4];
                ldsm4(q, st + off);
                bh[2 * p][0] = q[0]; bh[2 * p][1] = q[1];
                bh[2 * p + 1][0] = q[2]; bh[2 * p + 1][1] = q[3];
                ldsm4(q, st + 4096 + off);
                bl[2 * p][0] = q[0]; bl[2 * p][1] = q[1];
                bl[2 * p + 1][0] = q[2]; bl[2 * p + 1][1] = q[3];
            }
#pragma unroll
            for (int na = 0; na < 4; na++) {
                mma_bf16(acc[na], ah, bh[na]);
                mma_bf16(acc[na], ah, bl[na]);
                mma_bf16(acc[na], al, bh[na]);
            }
        }
    }

    // epilogue: h = sigmoid(acc + opre + b_o) * ct
#pragma unroll
    for (int half = 0; half < 2; half++) {
        const int gm = m0 + wm * 16 + (l >> 2) + half * 8;
#pragma unroll
        for (int na = 0; na < 4; na++) {
            const int col = n0 + wn * 32 + na * 8 + (l & 3) * 2;
            const float2 op = *(const float2*)(g_opre + (size_t)gm * NS + col);
            const float2 ct = *(const float2*)(g_ct + (size_t)gm * NS + col);
            float v0 = sigmoidf_(acc[na][half * 2 + 0] + op.x + b_o[col]) * ct.x;
            float v1 = sigmoidf_(acc[na][half * 2 + 1] + op.y + b_o[col + 1]) * ct.y;
            *(float2*)(h_out + (size_t)gm * NS + col) = make_float2(v0, v1);
        }
    }
#undef LOAD_STAGE3
}

// ============================================================================
extern "C" void kernel_launch(void* const* d_in, const int* in_sizes, int n_in,
                              void* d_out, int out_size)
{
    const float* x_i     = (const float*)d_in[0];
    const float* h_i     = (const float*)d_in[1];
    const float* S_i     = (const float*)d_in[2];
    const float* W_fste  = (const float*)d_in[3];
    const float* b_fste  = (const float*)d_in[4];
    const float* W_ffreq = (const float*)d_in[5];
    const float* b_ffreq = (const float*)d_in[6];
    const float* W_i     = (const float*)d_in[7];
    const float* b_i     = (const float*)d_in[8];
    const float* W_c     = (const float*)d_in[9];
    const float* b_c     = (const float*)d_in[10];
    const float* u_a     = (const float*)d_in[11];
    const float* b_a     = (const float*)d_in[12];
    const float* W_o     = (const float*)d_in[13];
    const float* b_o     = (const float*)d_in[14];
    const int*   t_ptr   = (const int*)d_in[15];

    float* out = (float*)d_out;
    float* h_out = out;                        // [B, NS]
    float* S_out = out + (size_t)B_ * NS;      // [B, 2, NS, NF]

    cudaFuncSetAttribute(gemm1_mma_kernel, cudaFuncAttributeMaxDynamicSharedMemorySize,
                         MMA_SMEM_TOTAL);
    cudaFuncSetAttribute(gemm3_mma_kernel, cudaFuncAttributeMaxDynamicSharedMemorySize,
                         MMA_SMEM_TOTAL);

    // 0) pack operands to bf16 hi/lo (single launch; includes W_o c-part)
    pack_all_kernel<<<PACKX_BLOCKS + PACKW_BLOCKS + PACKW2_BLOCKS, 256>>>(
        x_i, h_i, W_fste, W_ffreq, W_i, W_c, W_o);
    // 1) gate GEMM on HMMA tensor cores (bf16x3, 16x32 warp tile)
    {
        dim3 grid(NTOT / 64, B_ / 64);         // (17, 32)
        gemm1_mma_kernel<<<grid, 256, MMA_SMEM_TOTAL>>>(b_fste, b_ffreq, b_i, b_c);
    }
    // 2) fused S update + amplitude reduction + c_t (+ bf16 pack of c_t)
    {
        const int warps = B_ * NS / 4;
        dim3 grid(warps / 8);
        s_update_kernel<<<grid, 256>>>(S_i, S_out, u_a, b_a, t_ptr);
    }
    // 3) output GEMM on HMMA tensor cores (bf16x3)
    {
        dim3 grid(NS / 64, B_ / 64);           // (4, 32) = 128 CTAs
        gemm3_mma_kernel<<<grid, 256, MMA_SMEM_TOTAL>>>(b_o, h_out);
    }
}